// round 2
// baseline (speedup 1.0000x reference)
#include <cuda_runtime.h>

// Problem constants (fixed shapes for this problem instance)
#define NN   100000   // nodes
#define EE   400000   // edges
#define FIN  128      // input feature dim
#define FH   256      // hidden dim
#define GG   4096     // graphs
#define TT   12       // output tasks
#define NLAYER_REST 4 // layers 1..4

// ---------------- scratch (device globals; no allocation allowed) ----------
__device__ float g_bufA[NN * FH];   // h (layer input / BN output)
__device__ float g_bufB[NN * FH];   // agg / pre-BN scratch
__device__ float g_mid [NN * FH];   // MLP hidden
__device__ float g_stats[2 * FH];   // column sum / sumsq
__device__ float g_pool[GG * FH];   // pooled sums -> means
__device__ float g_cnt [GG];        // per-graph node counts
__device__ float g_gmid[GG * FH];   // predictor hidden

// ---------------- small utility kernels ------------------------------------
__global__ void k_zero(float* p, int n) {
    int i = blockIdx.x * blockDim.x + threadIdx.x;
    if (i < n) p[i] = 0.f;
}

__global__ void k_copy4(float* __restrict__ dst, const float* __restrict__ src, int n4) {
    int i = blockIdx.x * blockDim.x + threadIdx.x;
    if (i < n4) ((float4*)dst)[i] = ((const float4*)src)[i];
}

// scatter-add: agg[dst[e]] += x[src[e]], vectorized over feature dim
// NOTE: edge indices are int32 (JAX x64 disabled -> "int64" arrays are int32)
__global__ void k_scatter(float* __restrict__ agg, const float* __restrict__ X,
                          const int* __restrict__ src, const int* __restrict__ dst,
                          int fin, int total) {
    int i = blockIdx.x * blockDim.x + threadIdx.x;
    if (i >= total) return;
    int fchunks = fin >> 2;
    int e = i / fchunks;
    int f = (i - e * fchunks) << 2;
    int s = __ldg(&src[e]);
    int d = __ldg(&dst[e]);
    float4 v = *(const float4*)(X + (size_t)s * fin + f);
    float* p = agg + (size_t)d * fin + f;
    atomicAdd(p + 0, v.x);
    atomicAdd(p + 1, v.y);
    atomicAdd(p + 2, v.z);
    atomicAdd(p + 3, v.w);
}

// ---------------- tiled fp32 GEMM: C = A(MxK) @ B(KxNc) + bias, opt ReLU ---
#define BM 128
#define BN 64
#define BK 16
__global__ void __launch_bounds__(256)
k_gemm(const float* __restrict__ A, const float* __restrict__ B,
       const float* __restrict__ bias, float* __restrict__ C,
       int M, int K, int Nc, int relu) {
    __shared__ float As[BK][BM + 4];
    __shared__ float Bs[BK][BN];

    int tid = threadIdx.x;
    int tx = tid & 15;        // 0..15 -> 4 cols each
    int ty = tid >> 4;        // 0..15 -> 8 rows each
    int row0 = blockIdx.y * BM;
    int col0 = blockIdx.x * BN;

    float acc[8][4];
#pragma unroll
    for (int i = 0; i < 8; i++)
#pragma unroll
        for (int j = 0; j < 4; j++) acc[i][j] = 0.f;

    for (int k0 = 0; k0 < K; k0 += BK) {
        // load A tile (BM x BK), store transposed As[k][m]
#pragma unroll
        for (int i = 0; i < 8; i++) {
            int l = tid + i * 256;
            int r = l >> 4, c = l & 15;
            int gr = row0 + r;
            As[c][r] = (gr < M) ? A[(size_t)gr * K + (k0 + c)] : 0.f;
        }
        // load B tile (BK x BN)
#pragma unroll
        for (int i = 0; i < 4; i++) {
            int l = tid + i * 256;
            int r = l >> 6, c = l & 63;
            Bs[r][c] = B[(size_t)(k0 + r) * Nc + (col0 + c)];
        }
        __syncthreads();

#pragma unroll
        for (int kk = 0; kk < BK; kk++) {
            float a[8];
#pragma unroll
            for (int i = 0; i < 8; i++) a[i] = As[kk][ty * 8 + i];
            float4 b4 = *(const float4*)&Bs[kk][tx * 4];
            float b[4] = {b4.x, b4.y, b4.z, b4.w};
#pragma unroll
            for (int i = 0; i < 8; i++)
#pragma unroll
                for (int j = 0; j < 4; j++) acc[i][j] += a[i] * b[j];
        }
        __syncthreads();
    }

#pragma unroll
    for (int i = 0; i < 8; i++) {
        int gr = row0 + ty * 8 + i;
        if (gr >= M) continue;
#pragma unroll
        for (int j = 0; j < 4; j++) {
            int gc = col0 + tx * 4 + j;
            float v = acc[i][j] + bias[gc];
            if (relu) v = fmaxf(v, 0.f);
            C[(size_t)gr * Nc + gc] = v;
        }
    }
}

// ---------------- BatchNorm ------------------------------------------------
// per-column sum & sumsq over M rows (row-major X[M][FH])
__global__ void k_colstats(const float* __restrict__ X, float* __restrict__ stats, int M) {
    int c = threadIdx.x;  // 256 threads = 256 columns
    float s = 0.f, s2 = 0.f;
    for (int r = blockIdx.x; r < M; r += gridDim.x) {
        float v = X[(size_t)r * FH + c];
        s += v;
        s2 += v * v;
    }
    atomicAdd(&stats[c], s);
    atomicAdd(&stats[FH + c], s2);
}

__global__ void k_bn_relu(const float* __restrict__ X, const float* __restrict__ stats,
                          const float* __restrict__ gamma, const float* __restrict__ beta,
                          float* __restrict__ Y, int M) {
    size_t idx = (size_t)blockIdx.x * blockDim.x + threadIdx.x;
    if (idx >= (size_t)M * FH) return;
    int c = (int)(idx & (FH - 1));
    float invM = 1.0f / (float)M;
    float mean = stats[c] * invM;
    float var = stats[FH + c] * invM - mean * mean;
    float inv = rsqrtf(var + 1e-5f);
    float v = (X[idx] - mean) * inv * gamma[c] + beta[c];
    Y[idx] = v > 0.f ? v : 0.f;
}

// ---------------- pooling --------------------------------------------------
__global__ void k_pool_scatter(const float* __restrict__ H, const int* __restrict__ batch,
                               float* __restrict__ pool) {
    int i = blockIdx.x * blockDim.x + threadIdx.x;  // over NN * (FH/4)
    if (i >= NN * (FH / 4)) return;
    int node = i >> 6;              // FH/4 = 64
    int f = (i & 63) << 2;
    int b = __ldg(&batch[node]);
    float4 v = *(const float4*)(H + (size_t)node * FH + f);
    float* p = pool + (size_t)b * FH + f;
    atomicAdd(p + 0, v.x);
    atomicAdd(p + 1, v.y);
    atomicAdd(p + 2, v.z);
    atomicAdd(p + 3, v.w);
}

__global__ void k_count(const int* __restrict__ batch, float* __restrict__ cnt) {
    int i = blockIdx.x * blockDim.x + threadIdx.x;
    if (i < NN) atomicAdd(&cnt[batch[i]], 1.0f);
}

__global__ void k_pool_div(float* __restrict__ pool, const float* __restrict__ cnt) {
    int i = blockIdx.x * blockDim.x + threadIdx.x;
    if (i >= GG * FH) return;
    float c = cnt[i >> 8];  // FH = 256
    pool[i] = pool[i] / fmaxf(c, 1.0f);
}

// ---------------- final head: out = gmid @ Wp2 + bp2 (256 -> 12) -----------
__global__ void k_final(const float* __restrict__ gmid, const float* __restrict__ Wp2,
                        const float* __restrict__ bp2, float* __restrict__ out) {
    int i = blockIdx.x * blockDim.x + threadIdx.x;
    if (i >= GG * TT) return;
    int g = i / TT, t = i - g * TT;
    const float* row = gmid + (size_t)g * FH;
    float acc = bp2[t];
#pragma unroll 8
    for (int k = 0; k < FH; k++) acc += row[k] * __ldg(&Wp2[k * TT + t]);
    out[i] = acc;
}

// ---------------- host driver ----------------------------------------------
static void run_layer(const float* hin, int fin,
                      const float* W1, const float* b1,
                      const float* W2, const float* b2,
                      const float* gamma, const float* beta,
                      const int* src, const int* dst,
                      float* agg /* also pre-BN scratch */, float* mid,
                      float* hout, float* stats) {
    // agg = hin  (self term: h = x + sum_neighbors)
    int n4 = NN * fin / 4;
    k_copy4<<<(n4 + 255) / 256, 256>>>(agg, hin, n4);
    // agg[dst] += hin[src]
    int sc = EE * (fin / 4);
    k_scatter<<<(sc + 255) / 256, 256>>>(agg, hin, src, dst, fin, sc);
    // mid = relu(agg @ W1 + b1)
    k_gemm<<<dim3(FH / BN, (NN + BM - 1) / BM), 256>>>(agg, W1, b1, mid, NN, fin, FH, 1);
    // agg(reused) = mid @ W2 + b2   (pre-BN activations)
    k_gemm<<<dim3(FH / BN, (NN + BM - 1) / BM), 256>>>(mid, W2, b2, agg, NN, FH, FH, 0);
    // batch-norm statistics + apply + relu
    k_zero<<<2, 256>>>(stats, 2 * FH);
    k_colstats<<<512, 256>>>(agg, stats, NN);
    k_bn_relu<<<NN, 256>>>(agg, stats, gamma, beta, hout, NN);
}

extern "C" void kernel_launch(void* const* d_in, const int* in_sizes, int n_in,
                              void* d_out, int out_size) {
    const float* x     = (const float*)d_in[0];
    const int*   ei    = (const int*)d_in[1];    // int32 (JAX x64 disabled)
    const int*   batch = (const int*)d_in[2];    // int32
    // d_in[3] = num_graphs (scalar, unused — fixed GG)
    const float* W1_0 = (const float*)d_in[4];
    const float* b1_0 = (const float*)d_in[5];
    const float* W2_0 = (const float*)d_in[6];
    const float* b2_0 = (const float*)d_in[7];
    const float* g_0  = (const float*)d_in[8];
    const float* be_0 = (const float*)d_in[9];
    const float* W1s  = (const float*)d_in[10];
    const float* b1s  = (const float*)d_in[11];
    const float* W2s  = (const float*)d_in[12];
    const float* b2s  = (const float*)d_in[13];
    const float* gs   = (const float*)d_in[14];
    const float* bes  = (const float*)d_in[15];
    const float* Wp1  = (const float*)d_in[16];
    const float* bp1  = (const float*)d_in[17];
    const float* Wp2  = (const float*)d_in[18];
    const float* bp2  = (const float*)d_in[19];
    float* out = (float*)d_out;

    const int* src = ei;        // edge_index[0]
    const int* dst = ei + EE;   // edge_index[1]

    float *bufA, *bufB, *mid, *stats, *pool, *cnt, *gmid;
    cudaGetSymbolAddress((void**)&bufA,  g_bufA);
    cudaGetSymbolAddress((void**)&bufB,  g_bufB);
    cudaGetSymbolAddress((void**)&mid,   g_mid);
    cudaGetSymbolAddress((void**)&stats, g_stats);
    cudaGetSymbolAddress((void**)&pool,  g_pool);
    cudaGetSymbolAddress((void**)&cnt,   g_cnt);
    cudaGetSymbolAddress((void**)&gmid,  g_gmid);

    // layer 0: 128 -> 256
    run_layer(x, FIN, W1_0, b1_0, W2_0, b2_0, g_0, be_0, src, dst, bufB, mid, bufA, stats);

    // layers 1..4: 256 -> 256
    for (int l = 0; l < NLAYER_REST; l++) {
        run_layer(bufA, FH,
                  W1s + (size_t)l * FH * FH, b1s + (size_t)l * FH,
                  W2s + (size_t)l * FH * FH, b2s + (size_t)l * FH,
                  gs + (size_t)l * FH, bes + (size_t)l * FH,
                  src, dst, bufB, mid, bufA, stats);
    }

    // global mean pool
    k_zero<<<(GG * FH + 255) / 256, 256>>>(pool, GG * FH);
    k_zero<<<(GG + 255) / 256, 256>>>(cnt, GG);
    k_pool_scatter<<<(NN * (FH / 4) + 255) / 256, 256>>>(bufA, batch, pool);
    k_count<<<(NN + 255) / 256, 256>>>(batch, cnt);
    k_pool_div<<<(GG * FH + 255) / 256, 256>>>(pool, cnt);

    // predictor: gmid = relu(pool @ Wp1 + bp1); out = gmid @ Wp2 + bp2
    k_gemm<<<dim3(FH / BN, (GG + BM - 1) / BM), 256>>>(pool, Wp1, bp1, gmid, GG, FH, FH, 1);
    k_final<<<(GG * TT + 127) / 128, 128>>>(gmid, Wp2, bp2, out);
}

// round 4
// speedup vs baseline: 1.3403x; 1.3403x over previous
#include <cuda_runtime.h>
#include <cuda_fp16.h>
#include <cstdint>

// Problem constants
#define NN   100000
#define EE   400000
#define FIN  128
#define FH   256
#define GG   4096
#define TT   12
#define NLAYER_REST 4

// ---------------- scratch (device globals) ----------------
__device__ float  g_h   [NN * FH];
__device__ float  g_agg [NN * FH];
__device__ __half g_aggH[NN * FH];
__device__ __half g_aggL[NN * FH];
__device__ __half g_midH[NN * FH];
__device__ __half g_midL[NN * FH];
__device__ __half g_wH[11 * FH * FH];   // weight slots, [N][K] layout (transposed)
__device__ __half g_wL[11 * FH * FH];
__device__ float  g_stats[2 * FH];
__device__ float  g_pool [GG * FH];
__device__ __half g_poolH[GG * FH];
__device__ __half g_poolL[GG * FH];
__device__ float  g_cnt[GG];
__device__ float  g_gmid[GG * FH];

__device__ __forceinline__ uint32_t smem_u32(const void* p) {
    uint32_t a;
    asm("{ .reg .u64 t; cvta.to.shared.u64 t, %1; cvt.u32.u64 %0, t; }" : "=r"(a) : "l"(p));
    return a;
}

// ---------------- fp16 split-GEMM on mma.sync ----------------
// C[M,256] = A[M,K] @ W[K,256], A split into (Ah,Al), W pre-transposed+split
// to (Bh,Bl) with layout [N=256][K]. Three passes hh + hl + lh accumulated in
// fp32 mma accumulators.
// Block tile 128x128, 8 warps (4 M x 2 N), warp tile 32x64, BK=64.
// mode: 0 = bias, 1 = bias+relu, 2 = bias+relu+split-out (CoutH/CoutL)
#define NTOT 256
#define LDS_ST 72   // smem row stride in halves (64 + 8 pad -> conflict-free ldmatrix)

__global__ void __launch_bounds__(256, 2)
k_gemm_mma(const __half* __restrict__ Ah, const __half* __restrict__ Al,
           const __half* __restrict__ Bh, const __half* __restrict__ Bl,
           const float* __restrict__ bias,
           float* __restrict__ Cout, __half* __restrict__ CoutH, __half* __restrict__ CoutL,
           int M, int K, int mode) {
    __shared__ __half As[128 * LDS_ST];
    __shared__ __half Bs[128 * LDS_ST];

    const int tid = threadIdx.x;
    const int wid = tid >> 5, lid = tid & 31;
    const int wm = wid & 3, wn = wid >> 2;       // 4 x 2 warp grid
    const int row0 = blockIdx.y * 128;
    const int col0 = blockIdx.x * 128;

    float acc[2][8][4];
#pragma unroll
    for (int a = 0; a < 2; a++)
#pragma unroll
        for (int b = 0; b < 8; b++)
#pragma unroll
            for (int c = 0; c < 4; c++) acc[a][b][c] = 0.f;

    const uint32_t asb = smem_u32(As);
    const uint32_t bsb = smem_u32(Bs);

    // per-lane ldmatrix address bases
    const int q = lid >> 3, l8 = lid & 7;
    // A: q0:(r,k0) q1:(r+8,k0) q2:(r,k8) q3:(r+8,k8)
    const int a_row = wm * 32 + (q & 1) * 8 + l8;
    const int a_col = (q >> 1) * 8;
    // B: q0:(n,k0) q1:(n,k8) q2:(n+8,k0) q3:(n+8,k8)
    const int b_row = wn * 64 + (q >> 1) * 8 + l8;
    const int b_col = (q & 1) * 8;

    const int nchunk = K >> 6;  // K/64
    for (int pass = 0; pass < 3; pass++) {
        const __half* Ap = (pass == 2) ? Al : Ah;
        const __half* Bp = (pass == 1) ? Bl : Bh;
        for (int ck = 0; ck < nchunk; ck++) {
            const int k0 = ck << 6;
            __syncthreads();
            // load A chunk: 128 rows x 64 halves
#pragma unroll
            for (int i = 0; i < 4; i++) {
                int s = tid + i * 256;
                int r = s >> 3, c = s & 7;
                uint4 v = make_uint4(0, 0, 0, 0);
                if (row0 + r < M)
                    v = *(const uint4*)(Ap + (size_t)(row0 + r) * K + k0 + c * 8);
                *(uint4*)(As + r * LDS_ST + c * 8) = v;
            }
            // load B chunk: 128 rows (n = col0..col0+127) x 64 halves
#pragma unroll
            for (int i = 0; i < 4; i++) {
                int s = tid + i * 256;
                int r = s >> 3, c = s & 7;
                uint4 v = *(const uint4*)(Bp + (size_t)(col0 + r) * K + k0 + c * 8);
                *(uint4*)(Bs + r * LDS_ST + c * 8) = v;
            }
            __syncthreads();

#pragma unroll
            for (int ks = 0; ks < 4; ks++) {
                uint32_t af[2][4];
#pragma unroll
                for (int t = 0; t < 2; t++) {
                    uint32_t addr = asb + (uint32_t)(((a_row + t * 16) * LDS_ST + a_col + ks * 16) * 2);
                    asm volatile("ldmatrix.sync.aligned.m8n8.x4.shared.b16 {%0,%1,%2,%3}, [%4];"
                                 : "=r"(af[t][0]), "=r"(af[t][1]), "=r"(af[t][2]), "=r"(af[t][3])
                                 : "r"(addr));
                }
                uint32_t bf[8][2];
#pragma unroll
                for (int g = 0; g < 4; g++) {
                    uint32_t addr = bsb + (uint32_t)(((b_row + g * 16) * LDS_ST + b_col + ks * 16) * 2);
                    uint32_t r0, r1, r2, r3;
                    asm volatile("ldmatrix.sync.aligned.m8n8.x4.shared.b16 {%0,%1,%2,%3}, [%4];"
                                 : "=r"(r0), "=r"(r1), "=r"(r2), "=r"(r3)
                                 : "r"(addr));
                    bf[2 * g][0] = r0; bf[2 * g][1] = r1;
                    bf[2 * g + 1][0] = r2; bf[2 * g + 1][1] = r3;
                }
#pragma unroll
                for (int tm = 0; tm < 2; tm++)
#pragma unroll
                    for (int tn = 0; tn < 8; tn++) {
                        asm volatile(
                            "mma.sync.aligned.m16n8k16.row.col.f32.f16.f16.f32 "
                            "{%0,%1,%2,%3}, {%4,%5,%6,%7}, {%8,%9}, {%0,%1,%2,%3};"
                            : "+f"(acc[tm][tn][0]), "+f"(acc[tm][tn][1]),
                              "+f"(acc[tm][tn][2]), "+f"(acc[tm][tn][3])
                            : "r"(af[tm][0]), "r"(af[tm][1]), "r"(af[tm][2]), "r"(af[tm][3]),
                              "r"(bf[tn][0]), "r"(bf[tn][1]));
                    }
            }
        }
    }

    // epilogue
    const int erow = lid >> 2;
    const int ecol = (lid & 3) * 2;
#pragma unroll
    for (int tm = 0; tm < 2; tm++) {
#pragma unroll
        for (int half_m = 0; half_m < 2; half_m++) {
            int gr = row0 + wm * 32 + tm * 16 + erow + half_m * 8;
            if (gr >= M) continue;
#pragma unroll
            for (int tn = 0; tn < 8; tn++) {
                int gc = col0 + wn * 64 + tn * 8 + ecol;
                float v0 = acc[tm][tn][half_m * 2 + 0] + bias[gc];
                float v1 = acc[tm][tn][half_m * 2 + 1] + bias[gc + 1];
                if (mode >= 1) { v0 = fmaxf(v0, 0.f); v1 = fmaxf(v1, 0.f); }
                if (mode == 2) {
                    __half h0 = __float2half_rn(v0), h1 = __float2half_rn(v1);
                    __half l0 = __float2half_rn(v0 - __half2float(h0));
                    __half l1 = __float2half_rn(v1 - __half2float(h1));
                    *(__half2*)(CoutH + (size_t)gr * NTOT + gc) = __halves2half2(h0, h1);
                    *(__half2*)(CoutL + (size_t)gr * NTOT + gc) = __halves2half2(l0, l1);
                } else {
                    *(float2*)(Cout + (size_t)gr * NTOT + gc) = make_float2(v0, v1);
                }
            }
        }
    }
}

// ---------------- elementwise / graph kernels ----------------
__global__ void k_zero(float* p, int n) {
    int i = blockIdx.x * blockDim.x + threadIdx.x;
    if (i < n) p[i] = 0.f;
}
__global__ void k_copy4(float* __restrict__ d, const float* __restrict__ s, int n4) {
    int i = blockIdx.x * blockDim.x + threadIdx.x;
    if (i < n4) ((float4*)d)[i] = ((const float4*)s)[i];
}
// split float -> (hi, lo) fp16 pair
__global__ void k_split(const float* __restrict__ X, __half* __restrict__ H,
                        __half* __restrict__ L, int n4) {
    int i = blockIdx.x * blockDim.x + threadIdx.x;
    if (i >= n4) return;
    float4 v = ((const float4*)X)[i];
    __half hx = __float2half_rn(v.x), hy = __float2half_rn(v.y);
    __half hz = __float2half_rn(v.z), hw = __float2half_rn(v.w);
    __half lx = __float2half_rn(v.x - __half2float(hx));
    __half ly = __float2half_rn(v.y - __half2float(hy));
    __half lz = __float2half_rn(v.z - __half2float(hz));
    __half lw = __float2half_rn(v.w - __half2float(hw));
    ((__half2*)H)[2 * i]     = __halves2half2(hx, hy);
    ((__half2*)H)[2 * i + 1] = __halves2half2(hz, hw);
    ((__half2*)L)[2 * i]     = __halves2half2(lx, ly);
    ((__half2*)L)[2 * i + 1] = __halves2half2(lz, lw);
}
// weight prep: W[K][N] row-major -> Wh/Wl [N][K] halves
__global__ void k_wprep(const float* __restrict__ W, __half* __restrict__ WhT,
                        __half* __restrict__ WlT, int K, int N) {
    int i = blockIdx.x * blockDim.x + threadIdx.x;
    if (i >= K * N) return;
    int k = i / N, n = i - k * N;
    float v = W[i];
    __half h = __float2half_rn(v);
    WhT[(size_t)n * K + k] = h;
    WlT[(size_t)n * K + k] = __float2half_rn(v - __half2float(h));
}

__global__ void k_scatter(float* __restrict__ agg, const float* __restrict__ X,
                          const int* __restrict__ src, const int* __restrict__ dst,
                          int fin, int total) {
    int i = blockIdx.x * blockDim.x + threadIdx.x;
    if (i >= total) return;
    int fchunks = fin >> 2;
    int e = i / fchunks;
    int f = (i - e * fchunks) << 2;
    int s = __ldg(&src[e]);
    int d = __ldg(&dst[e]);
    float4 v = *(const float4*)(X + (size_t)s * fin + f);
    float* p = agg + (size_t)d * fin + f;
    atomicAdd(p + 0, v.x);
    atomicAdd(p + 1, v.y);
    atomicAdd(p + 2, v.z);
    atomicAdd(p + 3, v.w);
}

__global__ void k_colstats(const float* __restrict__ X, float* __restrict__ stats, int M) {
    int c = threadIdx.x;
    float s = 0.f, s2 = 0.f;
    for (int r = blockIdx.x; r < M; r += gridDim.x) {
        float v = X[(size_t)r * FH + c];
        s += v; s2 += v * v;
    }
    atomicAdd(&stats[c], s);
    atomicAdd(&stats[FH + c], s2);
}

// BN + ReLU; writes h and also re-initializes agg for next layer's scatter
__global__ void k_bn_relu(const float* __restrict__ X, const float* __restrict__ stats,
                          const float* __restrict__ gamma, const float* __restrict__ beta,
                          float* __restrict__ Y, float* __restrict__ AggInit, int M) {
    size_t idx = (size_t)blockIdx.x * blockDim.x + threadIdx.x;
    if (idx >= (size_t)M * FH) return;
    int c = (int)(idx & (FH - 1));
    float invM = 1.0f / (float)M;
    float mean = stats[c] * invM;
    float var = stats[FH + c] * invM - mean * mean;
    float inv = rsqrtf(var + 1e-5f);
    float v = (X[idx] - mean) * inv * gamma[c] + beta[c];
    v = v > 0.f ? v : 0.f;
    Y[idx] = v;
    AggInit[idx] = v;
}

__global__ void k_pool_scatter(const float* __restrict__ H, const int* __restrict__ batch,
                               float* __restrict__ pool) {
    int i = blockIdx.x * blockDim.x + threadIdx.x;
    if (i >= NN * (FH / 4)) return;
    int node = i >> 6;
    int f = (i & 63) << 2;
    int b = __ldg(&batch[node]);
    float4 v = *(const float4*)(H + (size_t)node * FH + f);
    float* p = pool + (size_t)b * FH + f;
    atomicAdd(p + 0, v.x);
    atomicAdd(p + 1, v.y);
    atomicAdd(p + 2, v.z);
    atomicAdd(p + 3, v.w);
}
__global__ void k_count(const int* __restrict__ batch, float* __restrict__ cnt) {
    int i = blockIdx.x * blockDim.x + threadIdx.x;
    if (i < NN) atomicAdd(&cnt[batch[i]], 1.0f);
}
__global__ void k_pool_div(float* __restrict__ pool, const float* __restrict__ cnt) {
    int i = blockIdx.x * blockDim.x + threadIdx.x;
    if (i >= GG * FH) return;
    float c = cnt[i >> 8];
    pool[i] = pool[i] / fmaxf(c, 1.0f);
}
__global__ void k_final(const float* __restrict__ gmid, const float* __restrict__ Wp2,
                        const float* __restrict__ bp2, float* __restrict__ out) {
    int i = blockIdx.x * blockDim.x + threadIdx.x;
    if (i >= GG * TT) return;
    int g = i / TT, t = i - g * TT;
    const float* row = gmid + (size_t)g * FH;
    float acc = bp2[t];
#pragma unroll 8
    for (int k = 0; k < FH; k++) acc += row[k] * __ldg(&Wp2[k * TT + t]);
    out[i] = acc;
}

// ---------------- host driver ----------------
extern "C" void kernel_launch(void* const* d_in, const int* in_sizes, int n_in,
                              void* d_out, int out_size) {
    const float* x     = (const float*)d_in[0];
    const int*   ei    = (const int*)d_in[1];
    const int*   batch = (const int*)d_in[2];
    const float* W1_0 = (const float*)d_in[4];
    const float* b1_0 = (const float*)d_in[5];
    const float* W2_0 = (const float*)d_in[6];
    const float* b2_0 = (const float*)d_in[7];
    const float* g_0  = (const float*)d_in[8];
    const float* be_0 = (const float*)d_in[9];
    const float* W1s  = (const float*)d_in[10];
    const float* b1s  = (const float*)d_in[11];
    const float* W2s  = (const float*)d_in[12];
    const float* b2s  = (const float*)d_in[13];
    const float* gs   = (const float*)d_in[14];
    const float* bes  = (const float*)d_in[15];
    const float* Wp1  = (const float*)d_in[16];
    const float* bp1  = (const float*)d_in[17];
    const float* Wp2  = (const float*)d_in[18];
    const float* bp2  = (const float*)d_in[19];
    float* out = (float*)d_out;

    const int* src = ei;
    const int* dst = ei + EE;

    float *h, *agg, *stats, *pool, *cnt, *gmid;
    __half *aggH, *aggL, *midH, *midL, *wH, *wL, *poolH, *poolL;
    cudaGetSymbolAddress((void**)&h,     g_h);
    cudaGetSymbolAddress((void**)&agg,   g_agg);
    cudaGetSymbolAddress((void**)&aggH,  g_aggH);
    cudaGetSymbolAddress((void**)&aggL,  g_aggL);
    cudaGetSymbolAddress((void**)&midH,  g_midH);
    cudaGetSymbolAddress((void**)&midL,  g_midL);
    cudaGetSymbolAddress((void**)&wH,    g_wH);
    cudaGetSymbolAddress((void**)&wL,    g_wL);
    cudaGetSymbolAddress((void**)&stats, g_stats);
    cudaGetSymbolAddress((void**)&pool,  g_pool);
    cudaGetSymbolAddress((void**)&poolH, g_poolH);
    cudaGetSymbolAddress((void**)&poolL, g_poolL);
    cudaGetSymbolAddress((void**)&cnt,   g_cnt);
    cudaGetSymbolAddress((void**)&gmid,  g_gmid);

    const int SLOT = FH * FH;

    // weight prep: slots 0..9 = layer weights, 10 = Wp1
    k_wprep<<<(FIN * FH + 255) / 256, 256>>>(W1_0, wH + 0 * SLOT, wL + 0 * SLOT, FIN, FH);
    k_wprep<<<(FH * FH + 255) / 256, 256>>>(W2_0, wH + 1 * SLOT, wL + 1 * SLOT, FH, FH);
    for (int l = 0; l < NLAYER_REST; l++) {
        k_wprep<<<(FH * FH + 255) / 256, 256>>>(W1s + (size_t)l * SLOT,
                                                wH + (2 + 2 * l) * SLOT, wL + (2 + 2 * l) * SLOT, FH, FH);
        k_wprep<<<(FH * FH + 255) / 256, 256>>>(W2s + (size_t)l * SLOT,
                                                wH + (3 + 2 * l) * SLOT, wL + (3 + 2 * l) * SLOT, FH, FH);
    }
    k_wprep<<<(FH * FH + 255) / 256, 256>>>(Wp1, wH + 10 * SLOT, wL + 10 * SLOT, FH, FH);

    const int GRID_M = (NN + 127) / 128;  // 782

    for (int l = 0; l < 1 + NLAYER_REST; l++) {
        int fin = (l == 0) ? FIN : FH;
        const float* hin   = (l == 0) ? x : h;
        const float* b1    = (l == 0) ? b1_0 : b1s + (size_t)(l - 1) * FH;
        const float* b2    = (l == 0) ? b2_0 : b2s + (size_t)(l - 1) * FH;
        const float* gamma = (l == 0) ? g_0  : gs  + (size_t)(l - 1) * FH;
        const float* beta  = (l == 0) ? be_0 : bes + (size_t)(l - 1) * FH;
        const __half* w1H = wH + (size_t)(l == 0 ? 0 : 2 * l) * SLOT;
        const __half* w1L = wL + (size_t)(l == 0 ? 0 : 2 * l) * SLOT;
        const __half* w2H = wH + (size_t)(l == 0 ? 1 : 2 * l + 1) * SLOT;
        const __half* w2L = wL + (size_t)(l == 0 ? 1 : 2 * l + 1) * SLOT;

        if (l == 0) {
            int n4 = NN * fin / 4;
            k_copy4<<<(n4 + 255) / 256, 256>>>(agg, x, n4);
        }
        int sc = EE * (fin / 4);
        k_scatter<<<(sc + 255) / 256, 256>>>(agg, hin, src, dst, fin, sc);
        k_split<<<(NN * fin / 4 + 255) / 256, 256>>>(agg, aggH, aggL, NN * fin / 4);
        // mid = relu(agg @ W1 + b1), split fp16 outputs
        k_gemm_mma<<<dim3(2, GRID_M), 256>>>(aggH, aggL, w1H, w1L, b1,
                                             nullptr, midH, midL, NN, fin, 2);
        // pre-BN = mid @ W2 + b2 -> agg (float)
        k_gemm_mma<<<dim3(2, GRID_M), 256>>>(midH, midL, w2H, w2L, b2,
                                             agg, nullptr, nullptr, NN, FH, 0);
        k_zero<<<2, 256>>>(stats, 2 * FH);
        k_colstats<<<512, 256>>>(agg, stats, NN);
        k_bn_relu<<<NN, 256>>>(agg, stats, gamma, beta, h, agg, NN);
    }

    // global mean pool
    k_zero<<<(GG * FH + 255) / 256, 256>>>(pool, GG * FH);
    k_zero<<<(GG + 255) / 256, 256>>>(cnt, GG);
    k_pool_scatter<<<(NN * (FH / 4) + 255) / 256, 256>>>(h, batch, pool);
    k_count<<<(NN + 255) / 256, 256>>>(batch, cnt);
    k_pool_div<<<(GG * FH + 255) / 256, 256>>>(pool, cnt);

    // predictor
    k_split<<<(GG * FH / 4 + 255) / 256, 256>>>(pool, poolH, poolL, GG * FH / 4);
    k_gemm_mma<<<dim3(2, GG / 128), 256>>>(poolH, poolL, wH + 10 * SLOT, wL + 10 * SLOT, bp1,
                                           gmid, nullptr, nullptr, GG, FH, 1);
    k_final<<<(GG * TT + 127) / 128, 128>>>(gmid, Wp2, bp2, out);
}

// round 5
// speedup vs baseline: 2.1360x; 1.5937x over previous
#include <cuda_runtime.h>
#include <cuda_fp16.h>
#include <cstdint>

// Problem constants
#define NN   100000
#define EE   400000
#define FIN  128
#define FH   256
#define GG   4096
#define TT   12
#define NLAYER_REST 4
#define SCAN_B 1024
#define NB_SCAN ((NN + SCAN_B - 1) / SCAN_B)   // 98

// ---------------- scratch (device globals) ----------------
__device__ float  g_h   [NN * FH];
__device__ float  g_agg [NN * FH];      // pre-BN activations
__device__ __half g_aggH[NN * FH];
__device__ __half g_aggL[NN * FH];
__device__ __half g_midH[NN * FH];
__device__ __half g_midL[NN * FH];
__device__ __half g_wH[11 * FH * FH];
__device__ __half g_wL[11 * FH * FH];
__device__ float  g_stats[2 * FH];
__device__ float  g_pool [GG * FH];
__device__ __half g_poolH[GG * FH];
__device__ __half g_poolL[GG * FH];
__device__ float  g_cnt[GG];
__device__ float  g_gmid[GG * FH];
// CSR structures
__device__ int    g_deg[NN];
__device__ int    g_rowptr[NN + 1];
__device__ int    g_col[EE];
__device__ int    g_cursor[NN];
__device__ int    g_bsums[128];

__device__ __forceinline__ uint32_t smem_u32(const void* p) {
    uint32_t a;
    asm("{ .reg .u64 t; cvta.to.shared.u64 t, %1; cvt.u32.u64 %0, t; }" : "=r"(a) : "l"(p));
    return a;
}

// ---------------- CSR build ----------------
__global__ void k_zero_int(int* p, int n) {
    int i = blockIdx.x * blockDim.x + threadIdx.x;
    if (i < n) p[i] = 0;
}
__global__ void k_hist(const int* __restrict__ dst, int* __restrict__ deg) {
    int e = blockIdx.x * blockDim.x + threadIdx.x;
    if (e < EE) atomicAdd(&deg[dst[e]], 1);
}
__global__ void k_scan1(const int* __restrict__ deg, int* __restrict__ rowptr,
                        int* __restrict__ bsums, int n) {
    __shared__ int s[SCAN_B];
    int i = blockIdx.x * SCAN_B + threadIdx.x;
    int v = (i < n) ? deg[i] : 0;
    s[threadIdx.x] = v;
    __syncthreads();
    for (int off = 1; off < SCAN_B; off <<= 1) {
        int t = (threadIdx.x >= off) ? s[threadIdx.x - off] : 0;
        __syncthreads();
        s[threadIdx.x] += t;
        __syncthreads();
    }
    if (i < n) rowptr[i] = s[threadIdx.x] - v;  // exclusive
    if (threadIdx.x == SCAN_B - 1) bsums[blockIdx.x] = s[SCAN_B - 1];
}
__global__ void k_scan2(int* __restrict__ bsums, int nb) {
    __shared__ int s[128];
    int v = (threadIdx.x < nb) ? bsums[threadIdx.x] : 0;
    s[threadIdx.x] = v;
    __syncthreads();
    for (int off = 1; off < 128; off <<= 1) {
        int t = (threadIdx.x >= off) ? s[threadIdx.x - off] : 0;
        __syncthreads();
        s[threadIdx.x] += t;
        __syncthreads();
    }
    if (threadIdx.x < nb) bsums[threadIdx.x] = s[threadIdx.x] - v;  // exclusive
}
__global__ void k_scan3(int* __restrict__ rowptr, const int* __restrict__ bsums, int n) {
    int i = blockIdx.x * blockDim.x + threadIdx.x;
    if (i < n) rowptr[i] += bsums[i / SCAN_B];
    if (i == 0) rowptr[n] = EE;
}
__global__ void k_fill(const int* __restrict__ src, const int* __restrict__ dst,
                       const int* __restrict__ rowptr, int* __restrict__ cursor,
                       int* __restrict__ col) {
    int e = blockIdx.x * blockDim.x + threadIdx.x;
    if (e >= EE) return;
    int d = dst[e];
    int p = atomicAdd(&cursor[d], 1);
    col[rowptr[d] + p] = src[e];
}

// ---------------- aggregation: agg = X[n] + sum_neighbors, fp16-split out ---
__global__ void k_agg_split(const float* __restrict__ X, const int* __restrict__ rowptr,
                            const int* __restrict__ col, __half* __restrict__ H,
                            __half* __restrict__ L, int fin, int total) {
    int i = blockIdx.x * blockDim.x + threadIdx.x;
    if (i >= total) return;
    int fc = fin >> 2;
    int node = i / fc;
    int f = (i - node * fc) << 2;
    int beg = __ldg(&rowptr[node]);
    int end = __ldg(&rowptr[node + 1]);
    float4 a = *(const float4*)(X + (size_t)node * fin + f);
    for (int e = beg; e < end; e++) {
        int s = __ldg(&col[e]);
        float4 v = *(const float4*)(X + (size_t)s * fin + f);
        a.x += v.x; a.y += v.y; a.z += v.z; a.w += v.w;
    }
    __half hx = __float2half_rn(a.x), hy = __float2half_rn(a.y);
    __half hz = __float2half_rn(a.z), hw = __float2half_rn(a.w);
    __half lx = __float2half_rn(a.x - __half2float(hx));
    __half ly = __float2half_rn(a.y - __half2float(hy));
    __half lz = __float2half_rn(a.z - __half2float(hz));
    __half lw = __float2half_rn(a.w - __half2float(hw));
    size_t o2 = ((size_t)node * fin + f) >> 1;
    ((__half2*)H)[o2]     = __halves2half2(hx, hy);
    ((__half2*)H)[o2 + 1] = __halves2half2(hz, hw);
    ((__half2*)L)[o2]     = __halves2half2(lx, ly);
    ((__half2*)L)[o2 + 1] = __halves2half2(lz, lw);
}

// ---------------- fp16 split-GEMM on mma.sync ----------------
// mode: 0 = bias (+fused column stats if stats!=null), 1 = bias+relu,
//       2 = bias+relu+split-out
#define NTOT 256
#define LDS_ST 72

__global__ void __launch_bounds__(256, 2)
k_gemm_mma(const __half* __restrict__ Ah, const __half* __restrict__ Al,
           const __half* __restrict__ Bh, const __half* __restrict__ Bl,
           const float* __restrict__ bias,
           float* __restrict__ Cout, __half* __restrict__ CoutH, __half* __restrict__ CoutL,
           float* __restrict__ stats,
           int M, int K, int mode) {
    __shared__ __half As[128 * LDS_ST];
    __shared__ __half Bs[128 * LDS_ST];

    const int tid = threadIdx.x;
    const int wid = tid >> 5, lid = tid & 31;
    const int wm = wid & 3, wn = wid >> 2;
    const int row0 = blockIdx.y * 128;
    const int col0 = blockIdx.x * 128;

    float acc[2][8][4];
#pragma unroll
    for (int a = 0; a < 2; a++)
#pragma unroll
        for (int b = 0; b < 8; b++)
#pragma unroll
            for (int c = 0; c < 4; c++) acc[a][b][c] = 0.f;

    const uint32_t asb = smem_u32(As);
    const uint32_t bsb = smem_u32(Bs);

    const int q = lid >> 3, l8 = lid & 7;
    const int a_row = wm * 32 + (q & 1) * 8 + l8;
    const int a_col = (q >> 1) * 8;
    const int b_row = wn * 64 + (q >> 1) * 8 + l8;
    const int b_col = (q & 1) * 8;

    const int nchunk = K >> 6;
    for (int pass = 0; pass < 3; pass++) {
        const __half* Ap = (pass == 2) ? Al : Ah;
        const __half* Bp = (pass == 1) ? Bl : Bh;
        for (int ck = 0; ck < nchunk; ck++) {
            const int k0 = ck << 6;
            __syncthreads();
#pragma unroll
            for (int i = 0; i < 4; i++) {
                int s = tid + i * 256;
                int r = s >> 3, c = s & 7;
                uint4 v = make_uint4(0, 0, 0, 0);
                if (row0 + r < M)
                    v = *(const uint4*)(Ap + (size_t)(row0 + r) * K + k0 + c * 8);
                *(uint4*)(As + r * LDS_ST + c * 8) = v;
            }
#pragma unroll
            for (int i = 0; i < 4; i++) {
                int s = tid + i * 256;
                int r = s >> 3, c = s & 7;
                uint4 v = *(const uint4*)(Bp + (size_t)(col0 + r) * K + k0 + c * 8);
                *(uint4*)(Bs + r * LDS_ST + c * 8) = v;
            }
            __syncthreads();

#pragma unroll
            for (int ks = 0; ks < 4; ks++) {
                uint32_t af[2][4];
#pragma unroll
                for (int t = 0; t < 2; t++) {
                    uint32_t addr = asb + (uint32_t)(((a_row + t * 16) * LDS_ST + a_col + ks * 16) * 2);
                    asm volatile("ldmatrix.sync.aligned.m8n8.x4.shared.b16 {%0,%1,%2,%3}, [%4];"
                                 : "=r"(af[t][0]), "=r"(af[t][1]), "=r"(af[t][2]), "=r"(af[t][3])
                                 : "r"(addr));
                }
                uint32_t bf[8][2];
#pragma unroll
                for (int g = 0; g < 4; g++) {
                    uint32_t addr = bsb + (uint32_t)(((b_row + g * 16) * LDS_ST + b_col + ks * 16) * 2);
                    uint32_t r0, r1, r2, r3;
                    asm volatile("ldmatrix.sync.aligned.m8n8.x4.shared.b16 {%0,%1,%2,%3}, [%4];"
                                 : "=r"(r0), "=r"(r1), "=r"(r2), "=r"(r3)
                                 : "r"(addr));
                    bf[2 * g][0] = r0; bf[2 * g][1] = r1;
                    bf[2 * g + 1][0] = r2; bf[2 * g + 1][1] = r3;
                }
#pragma unroll
                for (int tm = 0; tm < 2; tm++)
#pragma unroll
                    for (int tn = 0; tn < 8; tn++) {
                        asm volatile(
                            "mma.sync.aligned.m16n8k16.row.col.f32.f16.f16.f32 "
                            "{%0,%1,%2,%3}, {%4,%5,%6,%7}, {%8,%9}, {%0,%1,%2,%3};"
                            : "+f"(acc[tm][tn][0]), "+f"(acc[tm][tn][1]),
                              "+f"(acc[tm][tn][2]), "+f"(acc[tm][tn][3])
                            : "r"(af[tm][0]), "r"(af[tm][1]), "r"(af[tm][2]), "r"(af[tm][3]),
                              "r"(bf[tn][0]), "r"(bf[tn][1]));
                    }
            }
        }
    }

    // epilogue
    const int erow = lid >> 2;
    const int ecol = (lid & 3) * 2;
    float ssum[8][2], ssq[8][2];
    if (stats) {
#pragma unroll
        for (int tn = 0; tn < 8; tn++) {
            ssum[tn][0] = ssum[tn][1] = 0.f;
            ssq[tn][0] = ssq[tn][1] = 0.f;
        }
    }
#pragma unroll
    for (int tm = 0; tm < 2; tm++) {
#pragma unroll
        for (int half_m = 0; half_m < 2; half_m++) {
            int gr = row0 + wm * 32 + tm * 16 + erow + half_m * 8;
            bool ok = (gr < M);
#pragma unroll
            for (int tn = 0; tn < 8; tn++) {
                int gc = col0 + wn * 64 + tn * 8 + ecol;
                float v0 = acc[tm][tn][half_m * 2 + 0] + bias[gc];
                float v1 = acc[tm][tn][half_m * 2 + 1] + bias[gc + 1];
                if (mode >= 1) { v0 = fmaxf(v0, 0.f); v1 = fmaxf(v1, 0.f); }
                if (ok) {
                    if (mode == 2) {
                        __half h0 = __float2half_rn(v0), h1 = __float2half_rn(v1);
                        __half l0 = __float2half_rn(v0 - __half2float(h0));
                        __half l1 = __float2half_rn(v1 - __half2float(h1));
                        *(__half2*)(CoutH + (size_t)gr * NTOT + gc) = __halves2half2(h0, h1);
                        *(__half2*)(CoutL + (size_t)gr * NTOT + gc) = __halves2half2(l0, l1);
                    } else {
                        *(float2*)(Cout + (size_t)gr * NTOT + gc) = make_float2(v0, v1);
                    }
                }
                if (stats) {
                    float a0 = ok ? v0 : 0.f, a1 = ok ? v1 : 0.f;
                    ssum[tn][0] += a0;       ssum[tn][1] += a1;
                    ssq[tn][0]  += a0 * a0;  ssq[tn][1]  += a1 * a1;
                }
            }
        }
    }
    if (stats) {
        // reduce over the 8 erow lanes (same columns share lid&3)
#pragma unroll
        for (int tn = 0; tn < 8; tn++) {
#pragma unroll
            for (int j = 0; j < 2; j++) {
#pragma unroll
                for (int o = 4; o < 32; o <<= 1) {
                    ssum[tn][j] += __shfl_xor_sync(0xffffffffu, ssum[tn][j], o);
                    ssq[tn][j]  += __shfl_xor_sync(0xffffffffu, ssq[tn][j], o);
                }
            }
        }
        if (erow == 0) {
#pragma unroll
            for (int tn = 0; tn < 8; tn++) {
                int gc = col0 + wn * 64 + tn * 8 + ecol;
                atomicAdd(&stats[gc],          ssum[tn][0]);
                atomicAdd(&stats[gc + 1],      ssum[tn][1]);
                atomicAdd(&stats[FH + gc],     ssq[tn][0]);
                atomicAdd(&stats[FH + gc + 1], ssq[tn][1]);
            }
        }
    }
}

// ---------------- elementwise kernels ----------------
__global__ void k_zero(float* p, int n) {
    int i = blockIdx.x * blockDim.x + threadIdx.x;
    if (i < n) p[i] = 0.f;
}
__global__ void k_split(const float* __restrict__ X, __half* __restrict__ H,
                        __half* __restrict__ L, int n4) {
    int i = blockIdx.x * blockDim.x + threadIdx.x;
    if (i >= n4) return;
    float4 v = ((const float4*)X)[i];
    __half hx = __float2half_rn(v.x), hy = __float2half_rn(v.y);
    __half hz = __float2half_rn(v.z), hw = __float2half_rn(v.w);
    __half lx = __float2half_rn(v.x - __half2float(hx));
    __half ly = __float2half_rn(v.y - __half2float(hy));
    __half lz = __float2half_rn(v.z - __half2float(hz));
    __half lw = __float2half_rn(v.w - __half2float(hw));
    ((__half2*)H)[2 * i]     = __halves2half2(hx, hy);
    ((__half2*)H)[2 * i + 1] = __halves2half2(hz, hw);
    ((__half2*)L)[2 * i]     = __halves2half2(lx, ly);
    ((__half2*)L)[2 * i + 1] = __halves2half2(lz, lw);
}
__global__ void k_wprep(const float* __restrict__ W, __half* __restrict__ WhT,
                        __half* __restrict__ WlT, int K, int N) {
    int i = blockIdx.x * blockDim.x + threadIdx.x;
    if (i >= K * N) return;
    int k = i / N, n = i - k * N;
    float v = W[i];
    __half h = __float2half_rn(v);
    WhT[(size_t)n * K + k] = h;
    WlT[(size_t)n * K + k] = __float2half_rn(v - __half2float(h));
}

__global__ void k_bn_relu(const float* __restrict__ X, const float* __restrict__ stats,
                          const float* __restrict__ gamma, const float* __restrict__ beta,
                          float* __restrict__ Y, int M) {
    size_t idx = (size_t)blockIdx.x * blockDim.x + threadIdx.x;
    if (idx >= (size_t)M * FH) return;
    int c = (int)(idx & (FH - 1));
    float invM = 1.0f / (float)M;
    float mean = stats[c] * invM;
    float var = stats[FH + c] * invM - mean * mean;
    float inv = rsqrtf(var + 1e-5f);
    float v = (X[idx] - mean) * inv * gamma[c] + beta[c];
    Y[idx] = v > 0.f ? v : 0.f;
}

__global__ void k_pool_scatter(const float* __restrict__ H, const int* __restrict__ batch,
                               float* __restrict__ pool) {
    int i = blockIdx.x * blockDim.x + threadIdx.x;
    if (i >= NN * (FH / 4)) return;
    int node = i >> 6;
    int f = (i & 63) << 2;
    int b = __ldg(&batch[node]);
    float4 v = *(const float4*)(H + (size_t)node * FH + f);
    float* p = pool + (size_t)b * FH + f;
    atomicAdd(p + 0, v.x);
    atomicAdd(p + 1, v.y);
    atomicAdd(p + 2, v.z);
    atomicAdd(p + 3, v.w);
}
__global__ void k_count(const int* __restrict__ batch, float* __restrict__ cnt) {
    int i = blockIdx.x * blockDim.x + threadIdx.x;
    if (i < NN) atomicAdd(&cnt[batch[i]], 1.0f);
}
__global__ void k_pool_div(float* __restrict__ pool, const float* __restrict__ cnt) {
    int i = blockIdx.x * blockDim.x + threadIdx.x;
    if (i >= GG * FH) return;
    float c = cnt[i >> 8];
    pool[i] = pool[i] / fmaxf(c, 1.0f);
}
__global__ void k_final(const float* __restrict__ gmid, const float* __restrict__ Wp2,
                        const float* __restrict__ bp2, float* __restrict__ out) {
    int i = blockIdx.x * blockDim.x + threadIdx.x;
    if (i >= GG * TT) return;
    int g = i / TT, t = i - g * TT;
    const float* row = gmid + (size_t)g * FH;
    float acc = bp2[t];
#pragma unroll 8
    for (int k = 0; k < FH; k++) acc += row[k] * __ldg(&Wp2[k * TT + t]);
    out[i] = acc;
}

// ---------------- host driver ----------------
extern "C" void kernel_launch(void* const* d_in, const int* in_sizes, int n_in,
                              void* d_out, int out_size) {
    const float* x     = (const float*)d_in[0];
    const int*   ei    = (const int*)d_in[1];
    const int*   batch = (const int*)d_in[2];
    const float* W1_0 = (const float*)d_in[4];
    const float* b1_0 = (const float*)d_in[5];
    const float* W2_0 = (const float*)d_in[6];
    const float* b2_0 = (const float*)d_in[7];
    const float* g_0  = (const float*)d_in[8];
    const float* be_0 = (const float*)d_in[9];
    const float* W1s  = (const float*)d_in[10];
    const float* b1s  = (const float*)d_in[11];
    const float* W2s  = (const float*)d_in[12];
    const float* b2s  = (const float*)d_in[13];
    const float* gs   = (const float*)d_in[14];
    const float* bes  = (const float*)d_in[15];
    const float* Wp1  = (const float*)d_in[16];
    const float* bp1  = (const float*)d_in[17];
    const float* Wp2  = (const float*)d_in[18];
    const float* bp2  = (const float*)d_in[19];
    float* out = (float*)d_out;

    const int* src = ei;
    const int* dst = ei + EE;

    float *h, *agg, *stats, *pool, *cnt, *gmid;
    __half *aggH, *aggL, *midH, *midL, *wH, *wL, *poolH, *poolL;
    int *deg, *rowptr, *col, *cursor, *bsums;
    cudaGetSymbolAddress((void**)&h,     g_h);
    cudaGetSymbolAddress((void**)&agg,   g_agg);
    cudaGetSymbolAddress((void**)&aggH,  g_aggH);
    cudaGetSymbolAddress((void**)&aggL,  g_aggL);
    cudaGetSymbolAddress((void**)&midH,  g_midH);
    cudaGetSymbolAddress((void**)&midL,  g_midL);
    cudaGetSymbolAddress((void**)&wH,    g_wH);
    cudaGetSymbolAddress((void**)&wL,    g_wL);
    cudaGetSymbolAddress((void**)&stats, g_stats);
    cudaGetSymbolAddress((void**)&pool,  g_pool);
    cudaGetSymbolAddress((void**)&poolH, g_poolH);
    cudaGetSymbolAddress((void**)&poolL, g_poolL);
    cudaGetSymbolAddress((void**)&cnt,   g_cnt);
    cudaGetSymbolAddress((void**)&gmid,  g_gmid);
    cudaGetSymbolAddress((void**)&deg,    g_deg);
    cudaGetSymbolAddress((void**)&rowptr, g_rowptr);
    cudaGetSymbolAddress((void**)&col,    g_col);
    cudaGetSymbolAddress((void**)&cursor, g_cursor);
    cudaGetSymbolAddress((void**)&bsums,  g_bsums);

    const int SLOT = FH * FH;

    // ---- CSR build ----
    k_zero_int<<<(NN + 255) / 256, 256>>>(deg, NN);
    k_zero_int<<<(NN + 255) / 256, 256>>>(cursor, NN);
    k_hist<<<(EE + 255) / 256, 256>>>(dst, deg);
    k_scan1<<<NB_SCAN, SCAN_B>>>(deg, rowptr, bsums, NN);
    k_scan2<<<1, 128>>>(bsums, NB_SCAN);
    k_scan3<<<(NN + 255) / 256, 256>>>(rowptr, bsums, NN);
    k_fill<<<(EE + 255) / 256, 256>>>(src, dst, rowptr, cursor, col);

    // ---- weight prep ----
    k_wprep<<<(FIN * FH + 255) / 256, 256>>>(W1_0, wH + 0 * SLOT, wL + 0 * SLOT, FIN, FH);
    k_wprep<<<(FH * FH + 255) / 256, 256>>>(W2_0, wH + 1 * SLOT, wL + 1 * SLOT, FH, FH);
    for (int l = 0; l < NLAYER_REST; l++) {
        k_wprep<<<(FH * FH + 255) / 256, 256>>>(W1s + (size_t)l * SLOT,
                                                wH + (2 + 2 * l) * SLOT, wL + (2 + 2 * l) * SLOT, FH, FH);
        k_wprep<<<(FH * FH + 255) / 256, 256>>>(W2s + (size_t)l * SLOT,
                                                wH + (3 + 2 * l) * SLOT, wL + (3 + 2 * l) * SLOT, FH, FH);
    }
    k_wprep<<<(FH * FH + 255) / 256, 256>>>(Wp1, wH + 10 * SLOT, wL + 10 * SLOT, FH, FH);

    const int GRID_M = (NN + 127) / 128;

    for (int l = 0; l < 1 + NLAYER_REST; l++) {
        int fin = (l == 0) ? FIN : FH;
        const float* hin   = (l == 0) ? x : h;
        const float* b1    = (l == 0) ? b1_0 : b1s + (size_t)(l - 1) * FH;
        const float* b2    = (l == 0) ? b2_0 : b2s + (size_t)(l - 1) * FH;
        const float* gamma = (l == 0) ? g_0  : gs  + (size_t)(l - 1) * FH;
        const float* beta  = (l == 0) ? be_0 : bes + (size_t)(l - 1) * FH;
        const __half* w1H = wH + (size_t)(l == 0 ? 0 : 2 * l) * SLOT;
        const __half* w1L = wL + (size_t)(l == 0 ? 0 : 2 * l) * SLOT;
        const __half* w2H = wH + (size_t)(l == 0 ? 1 : 2 * l + 1) * SLOT;
        const __half* w2L = wL + (size_t)(l == 0 ? 1 : 2 * l + 1) * SLOT;

        // CSR gather aggregation + fp16 split, no atomics
        int total = NN * (fin / 4);
        k_agg_split<<<(total + 255) / 256, 256>>>(hin, rowptr, col, aggH, aggL, fin, total);
        // mid = relu(agg @ W1 + b1), split fp16 outputs
        k_gemm_mma<<<dim3(2, GRID_M), 256>>>(aggH, aggL, w1H, w1L, b1,
                                             nullptr, midH, midL, nullptr, NN, fin, 2);
        // pre-BN = mid @ W2 + b2 -> agg (float), fused column stats
        k_zero<<<2, 256>>>(stats, 2 * FH);
        k_gemm_mma<<<dim3(2, GRID_M), 256>>>(midH, midL, w2H, w2L, b2,
                                             agg, nullptr, nullptr, stats, NN, FH, 0);
        k_bn_relu<<<NN, 256>>>(agg, stats, gamma, beta, h, NN);
    }

    // global mean pool
    k_zero<<<(GG * FH + 255) / 256, 256>>>(pool, GG * FH);
    k_zero<<<(GG + 255) / 256, 256>>>(cnt, GG);
    k_pool_scatter<<<(NN * (FH / 4) + 255) / 256, 256>>>(h, batch, pool);
    k_count<<<(NN + 255) / 256, 256>>>(batch, cnt);
    k_pool_div<<<(GG * FH + 255) / 256, 256>>>(pool, cnt);

    // predictor
    k_split<<<(GG * FH / 4 + 255) / 256, 256>>>(pool, poolH, poolL, GG * FH / 4);
    k_gemm_mma<<<dim3(2, GG / 128), 256>>>(poolH, poolL, wH + 10 * SLOT, wL + 10 * SLOT, bp1,
                                           gmid, nullptr, nullptr, nullptr, GG, FH, 1);
    k_final<<<(GG * TT + 127) / 128, 128>>>(gmid, Wp2, bp2, out);
}